// round 2
// baseline (speedup 1.0000x reference)
#include <cuda_runtime.h>

// EvolvingGNN: T=5, N=100000, E=1600000, D=H=64, FE=16.
// Key algebraic facts exploited:
//  (1) Only xs_out[-1] is consumed -> run GCN once with the LSTM weight after 5 steps.
//  (2) Edge MLP first layer factors: hid = relu(A[src] + B[dst] + ea@W1c + b1)
//      with per-node A = x@W1[0:64], B = x@W1[64:128].
// NOTE: edge_index arrives as int32 (JAX x64-disabled downgrades jnp.int64).

#define NMAX 100000
#define EMAX 1600000

// Scratch (device globals: allocation-free)
__device__ float g_Wt[64 * 64];        // evolving weight, layout [k][r] = w[k*64+r]
__device__ float g_h[64 * 64];         // lstm h, [r][k]
__device__ float g_c[64 * 64];         // lstm c, [r][k]
__device__ float g_deg[NMAX];
__device__ float g_dinv[NMAX];
__device__ float g_xw[NMAX * 64];      // xs[4] @ W
__device__ float g_agg[NMAX * 64];     // GCN aggregation
__device__ float g_A[NMAX * 64];       // relu(agg) @ W1a
__device__ float g_B[NMAX * 64];       // relu(agg) @ W1b

__device__ __forceinline__ float sigmoidf(float x) { return 1.0f / (1.0f + expf(-x)); }

// ---------------- LSTM weight evolution: one step per launch ----------------
__global__ void lstm_step_kernel(const float* __restrict__ w0,
                                 const float* __restrict__ w_ih,
                                 const float* __restrict__ w_hh,
                                 const float* __restrict__ b_ih,
                                 const float* __restrict__ b_hh,
                                 int first) {
    __shared__ float xb[64], hr[64], gate[256];
    const float* w_in = first ? w0 : g_Wt;
    int r = blockIdx.x;
    int tid = threadIdx.x;
    if (tid < 64) {
        xb[tid] = w_in[tid * 64 + r];            // xb[r][k] = w[k][r]
        hr[tid] = first ? 0.f : g_h[r * 64 + tid];
    }
    __syncthreads();
    float acc = b_ih[tid] + b_hh[tid];
    const float* wi = w_ih + tid * 64;
    const float* wh = w_hh + tid * 64;
#pragma unroll 16
    for (int k = 0; k < 64; k++) acc += xb[k] * wi[k] + hr[k] * wh[k];
    gate[tid] = acc;
    __syncthreads();
    if (tid < 64) {
        float gi = sigmoidf(gate[tid]);
        float gf = sigmoidf(gate[64 + tid]);
        float gg = tanhf(gate[128 + tid]);
        float go = sigmoidf(gate[192 + tid]);
        float c0 = first ? 0.f : g_c[r * 64 + tid];
        float cn = gf * c0 + gi * gg;
        float hn = go * tanhf(cn);
        g_c[r * 64 + tid] = cn;
        g_h[r * 64 + tid] = hn;
        g_Wt[tid * 64 + r] = hn;                 // new W = h.T
    }
}

// ---------------- Degree / normalization ----------------
__global__ void deg_init_kernel(int n) {
    int i = blockIdx.x * blockDim.x + threadIdx.x;
    if (i < n) g_deg[i] = 1.0f;                  // self loop
}
__global__ void deg_count_kernel(const int* __restrict__ ei, int E) {
    int e = blockIdx.x * blockDim.x + threadIdx.x;
    if (e < E) atomicAdd(&g_deg[ei[E + e]], 1.0f);   // col = target index
}
__global__ void dinv_kernel(int n) {
    int i = blockIdx.x * blockDim.x + threadIdx.x;
    if (i < n) g_dinv[i] = rsqrtf(g_deg[i]);     // deg >= 1 always
}

// ---------------- xw = xs[last] @ W   (N x 64 @ 64 x 64) ----------------
__global__ void xw_kernel(const float* __restrict__ x, int n) {
    __shared__ float Ws[64 * 64];
    __shared__ float Xs[16 * 64];
    int tid = threadIdx.x;
    for (int i = tid; i < 4096; i += 256) Ws[i] = g_Wt[i];
    int row0 = blockIdx.x * 16;
    for (int i = tid; i < 1024; i += 256) {
        int rr = i >> 6, cc = i & 63;
        int nn = row0 + rr;
        Xs[i] = (nn < n) ? x[(size_t)nn * 64 + cc] : 0.f;
    }
    __syncthreads();
    int jr = (tid & 15) * 4;
    int rr = tid >> 4;
    float a0 = 0, a1 = 0, a2 = 0, a3 = 0;
    const float* xr = Xs + rr * 64;
#pragma unroll 8
    for (int k = 0; k < 64; k++) {
        float xv = xr[k];
        const float* wk = Ws + k * 64 + jr;
        a0 += xv * wk[0]; a1 += xv * wk[1]; a2 += xv * wk[2]; a3 += xv * wk[3];
    }
    int nn = row0 + rr;
    if (nn < n) *(float4*)(g_xw + (size_t)nn * 64 + jr) = make_float4(a0, a1, a2, a3);
}

// ---------------- agg init with self-loop contribution ----------------
__global__ void agg_init_kernel(int n) {
    int idx = blockIdx.x * blockDim.x + threadIdx.x;
    if (idx < n * 64) {
        int nd = idx >> 6;
        float dv = g_dinv[nd];
        g_agg[idx] = dv * dv * g_xw[idx];
    }
}

// ---------------- edge scatter: agg[dst] += dinv[src]*dinv[dst]*xw[src] ----------------
__global__ void scatter_kernel(const int* __restrict__ ei, int E) {
    int w = (blockIdx.x * blockDim.x + threadIdx.x) >> 5;
    int lane = threadIdx.x & 31;
    if (w >= E) return;
    int src = ei[w];
    int dst = ei[E + w];
    float coef = g_dinv[src] * g_dinv[dst];
    float2 v = *(const float2*)(g_xw + (size_t)src * 64 + 2 * lane);
    atomicAdd(&g_agg[(size_t)dst * 64 + 2 * lane], coef * v.x);
    atomicAdd(&g_agg[(size_t)dst * 64 + 2 * lane + 1], coef * v.y);
}

// ---------------- A,B = relu(agg) @ W1[0:64], @ W1[64:128] ----------------
__global__ void ab_kernel(const float* __restrict__ w1, int n) {
    __shared__ float Wa[64 * 64];
    __shared__ float Wb[64 * 64];
    __shared__ float Xs[16 * 64];
    int tid = threadIdx.x;
    for (int i = tid; i < 4096; i += 256) { Wa[i] = w1[i]; Wb[i] = w1[4096 + i]; }
    int row0 = blockIdx.x * 16;
    for (int i = tid; i < 1024; i += 256) {
        int rr = i >> 6, cc = i & 63;
        int nn = row0 + rr;
        Xs[i] = (nn < n) ? fmaxf(g_agg[(size_t)nn * 64 + cc], 0.f) : 0.f;  // relu
    }
    __syncthreads();
    int jr = (tid & 15) * 4;
    int rr = tid >> 4;
    float a0 = 0, a1 = 0, a2 = 0, a3 = 0;
    float b0 = 0, b1v = 0, b2v = 0, b3 = 0;
    const float* xr = Xs + rr * 64;
#pragma unroll 4
    for (int k = 0; k < 64; k++) {
        float xv = xr[k];
        const float* wa = Wa + k * 64 + jr;
        const float* wb = Wb + k * 64 + jr;
        a0 += xv * wa[0]; a1 += xv * wa[1]; a2 += xv * wa[2]; a3 += xv * wa[3];
        b0 += xv * wb[0]; b1v += xv * wb[1]; b2v += xv * wb[2]; b3 += xv * wb[3];
    }
    int nn = row0 + rr;
    if (nn < n) {
        *(float4*)(g_A + (size_t)nn * 64 + jr) = make_float4(a0, a1, a2, a3);
        *(float4*)(g_B + (size_t)nn * 64 + jr) = make_float4(b0, b1v, b2v, b3);
    }
}

// ---------------- Edge MLP: logit = relu(A[src]+B[dst]+ea@W1c+b1) . w2 + b2 ----------------
__global__ void edge_mlp_kernel(const int* __restrict__ ei,
                                const float* __restrict__ ea,
                                const float* __restrict__ w1,
                                const float* __restrict__ b1,
                                const float* __restrict__ w2,
                                const float* __restrict__ b2,
                                float* __restrict__ out, int E) {
    __shared__ float Wc[16 * 64];
    __shared__ float b1s[64];
    __shared__ float w2s[64];
    __shared__ float b2s;
    int tid = threadIdx.x;
    for (int i = tid; i < 1024; i += 256) Wc[i] = w1[8192 + i];   // rows 128..143
    if (tid < 64) { b1s[tid] = b1[tid]; w2s[tid] = w2[tid]; }
    if (tid == 0) b2s = b2[0];
    __syncthreads();
    int e = (blockIdx.x * 256 + tid) >> 5;
    int lane = tid & 31;
    if (e >= E) return;
    int src = ei[e];
    int dst = ei[E + e];
    float a0 = g_A[(size_t)src * 64 + lane] + g_B[(size_t)dst * 64 + lane] + b1s[lane];
    float a1 = g_A[(size_t)src * 64 + lane + 32] + g_B[(size_t)dst * 64 + lane + 32] + b1s[lane + 32];
    float eav = (lane < 16) ? ea[(size_t)e * 16 + lane] : 0.f;
#pragma unroll
    for (int k = 0; k < 16; k++) {
        float ek = __shfl_sync(0xffffffffu, eav, k);
        a0 += ek * Wc[k * 64 + lane];
        a1 += ek * Wc[k * 64 + lane + 32];
    }
    a0 = fmaxf(a0, 0.f);
    a1 = fmaxf(a1, 0.f);
    float p = a0 * w2s[lane] + a1 * w2s[lane + 32];
#pragma unroll
    for (int off = 16; off; off >>= 1) p += __shfl_xor_sync(0xffffffffu, p, off);
    if (lane == 0) out[e] = p + b2s;
}

extern "C" void kernel_launch(void* const* d_in, const int* in_sizes, int n_in,
                              void* d_out, int out_size) {
    const float* xs = (const float*)d_in[0];
    const int* ei = (const int*)d_in[1];            // int32 (JAX x64 disabled)
    const float* ea = (const float*)d_in[2];
    const float* init_w = (const float*)d_in[3];
    const float* w_ih = (const float*)d_in[4];
    const float* w_hh = (const float*)d_in[5];
    const float* b_ih = (const float*)d_in[6];
    const float* b_hh = (const float*)d_in[7];
    const float* w1 = (const float*)d_in[8];
    const float* b1 = (const float*)d_in[9];
    const float* w2 = (const float*)d_in[10];
    const float* b2 = (const float*)d_in[11];
    float* out = (float*)d_out;

    int N = in_sizes[0] / (5 * 64);
    int E = in_sizes[1] / 2;

    // 1) LSTM weight evolution (5 sequential steps)
    lstm_step_kernel<<<64, 256>>>(init_w, w_ih, w_hh, b_ih, b_hh, 1);
    for (int t = 1; t < 5; t++)
        lstm_step_kernel<<<64, 256>>>(init_w, w_ih, w_hh, b_ih, b_hh, 0);

    // 2) GCN normalization
    deg_init_kernel<<<(N + 255) / 256, 256>>>(N);
    deg_count_kernel<<<(E + 255) / 256, 256>>>(ei, E);
    dinv_kernel<<<(N + 255) / 256, 256>>>(N);

    // 3) xw = xs[4] @ W
    xw_kernel<<<(N + 15) / 16, 256>>>(xs + (size_t)4 * N * 64, N);

    // 4) aggregation: self loops then edge scatter
    agg_init_kernel<<<(N * 64 + 255) / 256, 256>>>(N);
    scatter_kernel<<<(E + 7) / 8, 256>>>(ei, E);

    // 5) per-node MLP halves
    ab_kernel<<<(N + 15) / 16, 256>>>(w1, N);

    // 6) per-edge MLP + logit
    edge_mlp_kernel<<<(E + 7) / 8, 256>>>(ei, ea, w1, b1, w2, b2, out, E);
}

// round 3
// speedup vs baseline: 1.2378x; 1.2378x over previous
#include <cuda_runtime.h>

// EvolvingGNN: T=5, N=100000, E=1600000, D=H=64, FE=16.
//  (1) Only xs_out[-1] is consumed -> run GCN once with the LSTM weight after 5 steps.
//  (2) Edge MLP first layer factors: hid = relu(A[src] + B[dst] + ea@W1c + b1).
//  (3) LSTM blocks are independent across timesteps -> single launch, 5 internal steps.
//  (4) Scatter uses float4 vector atomics (red.global.add.v4.f32 on sm_90+).
// edge_index arrives as int32 (JAX x64-disabled downgrades jnp.int64).

#define NMAX 100000

// Scratch (device globals: allocation-free)
__device__ float g_Wt[64 * 64];        // final evolved weight, [k][r]
__device__ float g_deg[NMAX];
__device__ float g_dinv[NMAX];
__device__ float g_xws[NMAX * 64];     // dinv[n] * (xs[4] @ W)[n]
__device__ float g_agg[NMAX * 64];     // GCN aggregation
__device__ float g_A[NMAX * 64];       // relu(agg) @ W1[0:64]
__device__ float g_B[NMAX * 64];       // relu(agg) @ W1[64:128]

__device__ __forceinline__ float sigmoidf(float x) { return 1.0f / (1.0f + expf(-x)); }

// ---------------- LSTM: all 5 steps in one launch ----------------
// Block r evolves W column r; xb (the LSTM input row) == h row r after step 1,
// so the whole recurrence stays in shared memory. Weights stream from L1 after
// the first iteration.
__global__ void lstm_all_kernel(const float* __restrict__ w0,
                                const float* __restrict__ w_ih,
                                const float* __restrict__ w_hh,
                                const float* __restrict__ b_ih,
                                const float* __restrict__ b_hh) {
    __shared__ float xb[64], cr[64], gate[256];
    int r = blockIdx.x;
    int tid = threadIdx.x;
    if (tid < 64) {
        xb[tid] = w0[tid * 64 + r];
        cr[tid] = 0.f;
    }
    float bsum = b_ih[tid] + b_hh[tid];
    const float4* wi = (const float4*)(w_ih + tid * 64);
    const float4* wh = (const float4*)(w_hh + tid * 64);
    float h_prev = 0.f;                 // h[r][tid] for tid<64 (step>=1 input is xb anyway)
    (void)h_prev;
    for (int t = 0; t < 5; t++) {
        __syncthreads();
        float acc = bsum;
        // gates row tid: sum_k xb[k]*w_ih[tid][k] + (t? xb==h : h=0 handled via xb/hr)
        // note: for t>=1 the hidden state h equals xb (new W column == h row),
        // but for t==0 h=0 while xb=w0. So track them separately via hr flag.
#pragma unroll
        for (int k4 = 0; k4 < 16; k4++) {
            float4 a = wi[k4];
            float4 b = wh[k4];
            float x0 = xb[4 * k4], x1 = xb[4 * k4 + 1], x2 = xb[4 * k4 + 2], x3 = xb[4 * k4 + 3];
            acc += a.x * x0 + a.y * x1 + a.z * x2 + a.w * x3;
            if (t > 0)  // h == xb for t>=1; h==0 at t==0
                acc += b.x * x0 + b.y * x1 + b.z * x2 + b.w * x3;
        }
        gate[tid] = acc;
        __syncthreads();
        if (tid < 64) {
            float gi = sigmoidf(gate[tid]);
            float gf = sigmoidf(gate[64 + tid]);
            float gg = tanhf(gate[128 + tid]);
            float go = sigmoidf(gate[192 + tid]);
            float cn = gf * cr[tid] + gi * gg;
            float hn = go * tanhf(cn);
            cr[tid] = cn;
            xb[tid] = hn;               // next input == h row r == new W column r
        }
    }
    if (tid < 64) g_Wt[tid * 64 + r] = xb[tid];
}

// ---------------- Degree / normalization ----------------
__global__ void deg_init_kernel(int n) {
    int i = blockIdx.x * blockDim.x + threadIdx.x;
    if (i < n) g_deg[i] = 1.0f;                  // self loop
}
__global__ void deg_count_kernel(const int* __restrict__ ei, int E) {
    int e = blockIdx.x * blockDim.x + threadIdx.x;
    if (e < E) atomicAdd(&g_deg[ei[E + e]], 1.0f);
}
__global__ void dinv_kernel(int n) {
    int i = blockIdx.x * blockDim.x + threadIdx.x;
    if (i < n) g_dinv[i] = rsqrtf(g_deg[i]);
}

// ---------------- xws = dinv * (xs[last] @ W); agg = dinv * xws (self loop) ----------------
__global__ void xw_kernel(const float* __restrict__ x, int n) {
    __shared__ float Ws[64 * 64];
    __shared__ float Xs[16 * 64];
    int tid = threadIdx.x;
    for (int i = tid; i < 4096; i += 256) Ws[i] = g_Wt[i];
    int row0 = blockIdx.x * 16;
    for (int i = tid; i < 1024; i += 256) {
        int rr = i >> 6, cc = i & 63;
        int nn = row0 + rr;
        Xs[i] = (nn < n) ? x[(size_t)nn * 64 + cc] : 0.f;
    }
    __syncthreads();
    int jr = (tid & 15) * 4;
    int rr = tid >> 4;
    float a0 = 0, a1 = 0, a2 = 0, a3 = 0;
    const float* xr = Xs + rr * 64;
#pragma unroll 8
    for (int k = 0; k < 64; k++) {
        float xv = xr[k];
        const float* wk = Ws + k * 64 + jr;
        a0 += xv * wk[0]; a1 += xv * wk[1]; a2 += xv * wk[2]; a3 += xv * wk[3];
    }
    int nn = row0 + rr;
    if (nn < n) {
        float dv = g_dinv[nn];
        float4 s = make_float4(dv * a0, dv * a1, dv * a2, dv * a3);
        *(float4*)(g_xws + (size_t)nn * 64 + jr) = s;
        *(float4*)(g_agg + (size_t)nn * 64 + jr) =
            make_float4(dv * s.x, dv * s.y, dv * s.z, dv * s.w);
    }
}

// ---------------- edge scatter: agg[dst] += dinv[dst] * xws[src] ----------------
// 16 lanes per edge, float4 gather + float4 vector atomic (RED.128).
__global__ void scatter_kernel(const int* __restrict__ ei, int E) {
    int idx = blockIdx.x * blockDim.x + threadIdx.x;
    int e = idx >> 4;
    int l = idx & 15;
    if (e >= E) return;
    int src = ei[e];
    int dst = ei[E + e];
    float coef = g_dinv[dst];
    float4 v = *(const float4*)(g_xws + (size_t)src * 64 + 4 * l);
    float4 m = make_float4(coef * v.x, coef * v.y, coef * v.z, coef * v.w);
    atomicAdd((float4*)(g_agg + (size_t)dst * 64 + 4 * l), m);
}

// ---------------- A,B = relu(agg) @ W1[0:64], @ W1[64:128] ----------------
__global__ void ab_kernel(const float* __restrict__ w1, int n) {
    __shared__ float Wa[64 * 64];
    __shared__ float Wb[64 * 64];
    __shared__ float Xs[16 * 64];
    int tid = threadIdx.x;
    for (int i = tid; i < 4096; i += 256) { Wa[i] = w1[i]; Wb[i] = w1[4096 + i]; }
    int row0 = blockIdx.x * 16;
    for (int i = tid; i < 1024; i += 256) {
        int rr = i >> 6, cc = i & 63;
        int nn = row0 + rr;
        Xs[i] = (nn < n) ? fmaxf(g_agg[(size_t)nn * 64 + cc], 0.f) : 0.f;
    }
    __syncthreads();
    int jr = (tid & 15) * 4;
    int rr = tid >> 4;
    float a0 = 0, a1 = 0, a2 = 0, a3 = 0;
    float b0 = 0, b1v = 0, b2v = 0, b3 = 0;
    const float* xr = Xs + rr * 64;
#pragma unroll 4
    for (int k = 0; k < 64; k++) {
        float xv = xr[k];
        const float* wa = Wa + k * 64 + jr;
        const float* wb = Wb + k * 64 + jr;
        a0 += xv * wa[0]; a1 += xv * wa[1]; a2 += xv * wa[2]; a3 += xv * wa[3];
        b0 += xv * wb[0]; b1v += xv * wb[1]; b2v += xv * wb[2]; b3 += xv * wb[3];
    }
    int nn = row0 + rr;
    if (nn < n) {
        *(float4*)(g_A + (size_t)nn * 64 + jr) = make_float4(a0, a1, a2, a3);
        *(float4*)(g_B + (size_t)nn * 64 + jr) = make_float4(b0, b1v, b2v, b3);
    }
}

// ---------------- Edge MLP: logit = relu(A[src]+B[dst]+ea@W1c+b1) . w2 + b2 ----------------
// One warp per edge; lane handles hid[2*lane], hid[2*lane+1] via float2 loads.
__global__ void edge_mlp_kernel(const int* __restrict__ ei,
                                const float* __restrict__ ea,
                                const float* __restrict__ w1,
                                const float* __restrict__ b1,
                                const float* __restrict__ w2,
                                const float* __restrict__ b2,
                                float* __restrict__ out, int E) {
    __shared__ float Wc[16 * 64];
    __shared__ float b1s[64];
    __shared__ float w2s[64];
    __shared__ float b2s;
    int tid = threadIdx.x;
    for (int i = tid; i < 1024; i += 256) Wc[i] = w1[8192 + i];   // rows 128..143
    if (tid < 64) { b1s[tid] = b1[tid]; w2s[tid] = w2[tid]; }
    if (tid == 0) b2s = b2[0];
    __syncthreads();
    int e = (blockIdx.x * 256 + tid) >> 5;
    int lane = tid & 31;
    if (e >= E) return;
    int src = ei[e];
    int dst = ei[E + e];
    float2 av = *(const float2*)(g_A + (size_t)src * 64 + 2 * lane);
    float2 bv = *(const float2*)(g_B + (size_t)dst * 64 + 2 * lane);
    float h0 = av.x + bv.x + b1s[2 * lane];
    float h1 = av.y + bv.y + b1s[2 * lane + 1];
    float eav = (lane < 16) ? ea[(size_t)e * 16 + lane] : 0.f;
#pragma unroll
    for (int k = 0; k < 16; k++) {
        float ek = __shfl_sync(0xffffffffu, eav, k);
        float2 wv = *(const float2*)(Wc + k * 64 + 2 * lane);
        h0 += ek * wv.x;
        h1 += ek * wv.y;
    }
    h0 = fmaxf(h0, 0.f);
    h1 = fmaxf(h1, 0.f);
    float p = h0 * w2s[2 * lane] + h1 * w2s[2 * lane + 1];
#pragma unroll
    for (int off = 16; off; off >>= 1) p += __shfl_xor_sync(0xffffffffu, p, off);
    if (lane == 0) out[e] = p + b2s;
}

extern "C" void kernel_launch(void* const* d_in, const int* in_sizes, int n_in,
                              void* d_out, int out_size) {
    const float* xs = (const float*)d_in[0];
    const int* ei = (const int*)d_in[1];            // int32 (JAX x64 disabled)
    const float* ea = (const float*)d_in[2];
    const float* init_w = (const float*)d_in[3];
    const float* w_ih = (const float*)d_in[4];
    const float* w_hh = (const float*)d_in[5];
    const float* b_ih = (const float*)d_in[6];
    const float* b_hh = (const float*)d_in[7];
    const float* w1 = (const float*)d_in[8];
    const float* b1 = (const float*)d_in[9];
    const float* w2 = (const float*)d_in[10];
    const float* b2 = (const float*)d_in[11];
    float* out = (float*)d_out;

    int N = in_sizes[0] / (5 * 64);
    int E = in_sizes[1] / 2;

    // 1) LSTM weight evolution, all 5 steps in one launch
    lstm_all_kernel<<<64, 256>>>(init_w, w_ih, w_hh, b_ih, b_hh);

    // 2) GCN normalization
    deg_init_kernel<<<(N + 255) / 256, 256>>>(N);
    deg_count_kernel<<<(E + 255) / 256, 256>>>(ei, E);
    dinv_kernel<<<(N + 255) / 256, 256>>>(N);

    // 3) xws = dinv * (xs[4] @ W), agg initialized with self-loop term
    xw_kernel<<<(N + 15) / 16, 256>>>(xs + (size_t)4 * N * 64, N);

    // 4) edge scatter with float4 vector atomics
    scatter_kernel<<<(E * 16 + 255) / 256, 256>>>(ei, E);

    // 5) per-node MLP halves
    ab_kernel<<<(N + 15) / 16, 256>>>(w1, N);

    // 6) per-edge MLP + logit
    edge_mlp_kernel<<<(E + 7) / 8, 256>>>(ei, ea, w1, b1, w2, b2, out, E);
}